// round 15
// baseline (speedup 1.0000x reference)
#include <cuda_runtime.h>
#include <cuda_bf16.h>
#include <math.h>
#include <stdint.h>

#define Bb 64
#define Tt 12
#define Nn 512
#define Dd 2
#define NB (Nn*Bb)   // 32768 rows (row = node*64 + batch)
#define APN 4096     // uint32 per node per buffer (h-part only: [s2][mt4][kt4][lane32][rg4])

// ---------------- device scratch ----------------
__device__ float g_h[2][NB*64];          // ping-pong hidden state (fp32)
__device__ float g_s[NB*64];             // s = A^T h (fp32)
// h-part A fragments per step parity (kt 0..3 only)
__device__ uint32_t g_Ap[2][Nn*APN];
// B fragments: [split][ktile 8][ntile 32][lane 32][reg 2]
__device__ uint32_t g_Bp[2*8*32*64];
__device__ float g_cvec[192];            // b_msg @ W_ih_m^T
__device__ float g_Wx[384];              // x weights [d][o]
__device__ float g_csum[Nn];
__device__ int   g_colj[Nn*Nn];
__device__ float g_colw[Nn*Nn];
__device__ int   g_cnt[Nn];

__device__ __forceinline__ uint32_t packbf(__nv_bfloat16 lo, __nv_bfloat16 hi) {
    return ((uint32_t)__bfloat16_as_ushort(hi) << 16) | (uint32_t)__bfloat16_as_ushort(lo);
}
__device__ __forceinline__ void split2(float v, __nv_bfloat16& b1, __nv_bfloat16& b2) {
    b1 = __float2bfloat16_rn(v);
    b2 = __float2bfloat16_rn(v - __bfloat162float(b1));
}
// h-part fragment index for value-pair at (r local row, kp = k/2 < 32); s = split
__device__ __forceinline__ int frag_idx(int s, int r, int kp) {
    int mt = r >> 4, kt = kp >> 3, q = kp & 7;
    int lf = ((r & 7) << 2) + (q & 3);
    int rg = ((q >> 2) << 1) + ((r & 15) >> 3);
    return ((s*4 + mt)*4 + kt)*128 + lf*4 + rg;
}
__device__ __forceinline__ void store_frag(uint32_t* Apn, int r, int kp, float2 v) {
    __nv_bfloat16 lo1, lo2, hi1, hi2;
    split2(v.x, lo1, lo2);
    split2(v.y, hi1, hi2);
    Apn[frag_idx(0, r, kp)] = packbf(lo1, hi1);
    Apn[frag_idx(1, r, kp)] = packbf(lo2, hi2);
}

#define MMA16816(c, a, b) \
    asm volatile("mma.sync.aligned.m16n8k16.row.col.f32.bf16.bf16.f32 " \
        "{%0,%1,%2,%3}, {%4,%5,%6,%7}, {%8,%9}, {%0,%1,%2,%3};" \
        : "+f"((c)[0]), "+f"((c)[1]), "+f"((c)[2]), "+f"((c)[3]) \
        : "r"((a)[0]), "r"((a)[1]), "r"((a)[2]), "r"((a)[3]), \
          "r"((b)[0]), "r"((b)[1]))

// ---------------- prep: pack B fragments + tables ----------------
__global__ void prep_kernel(const float* __restrict__ W_hh,
                            const float* __restrict__ W_ih,
                            const float* __restrict__ W_msg,
                            const float* __restrict__ b_msg) {
    int idx = blockIdx.x * 256 + threadIdx.x;
    if (idx < 16384) {                      // (n 0..255) x (kpair 0..63)
        int n = idx >> 6, kp = idx & 63;
        int p = n >> 6, g = n & 63;
        float w[2];
        #pragma unroll
        for (int u = 0; u < 2; u++) {
            int k = 2*kp + u;
            float v = 0.f;
            if (k < 64) {
                if (p < 3) v = W_hh[(p*64 + g)*64 + k];
            } else {
                int ks = k - 64;
                if (p != 2) {
                    int o = (p == 3) ? (128 + g) : (p*64 + g);
                    float s = 0.f;
                    for (int m = 0; m < 64; m++) s += W_msg[m*64 + ks] * W_ih[o*66 + m];
                    v = s;
                }
            }
            w[u] = v;
        }
        __nv_bfloat16 lo1, lo2, hi1, hi2;
        split2(w[0], lo1, lo2);
        split2(w[1], hi1, hi2);
        int nt = n >> 3, kt = kp >> 3, q = kp & 7;
        int lane = ((n & 7) << 2) + (q & 3);
        int reg = q >> 2;
        g_Bp[((0*8 + kt)*32 + nt)*64 + lane*2 + reg] = packbf(lo1, hi1);
        g_Bp[((1*8 + kt)*32 + nt)*64 + lane*2 + reg] = packbf(lo2, hi2);
    } else if (idx < 16384 + 384) {          // Wx[d][o]
        int j = idx - 16384;
        int d = j / 192, o = j - d*192;
        g_Wx[j] = W_ih[o*66 + 64 + d];
    } else if (idx < 16384 + 384 + 192) {    // cvec
        int o = idx - 16384 - 384;
        float s = 0.f;
        for (int m = 0; m < 64; m++) s += b_msg[m] * W_ih[o*66 + m];
        g_cvec[o] = s;
    }
}

// ---------------- one-time: h0 -> h-fragments of buffer 0 ----------------
__global__ void init_frag(const float* __restrict__ h0) {
    int item = blockIdx.x * 256 + threadIdx.x;   // (n, r, kp<32): 512*64*32 = 1M
    #pragma unroll
    for (int it = 0; it < 4; it++, item += 262144) {
        int n = item >> 11;
        int rem = item & 2047;
        int r = rem >> 5, kp = rem & 31;
        float2 v = *(const float2*)(h0 + (((n << 6) + r) << 6) + (kp << 1));
        store_frag(g_Ap[0] + n*APN, r, kp, v);
    }
}

// ---------------- deterministic CSC build + column sums (zero-padded to 64) --
__global__ void build_csc(const float* __restrict__ adj) {
    int i = blockIdx.x;
    int j = threadIdx.x;
    if (j < 64) { g_colj[i*Nn + j] = 0; g_colw[i*Nn + j] = 0.f; }
    float w = adj[j*Nn + i];
    bool p = (w > 0.f);
    unsigned mask = __ballot_sync(0xffffffffu, p);
    int warp = j >> 5, lane = j & 31;
    __shared__ int wcnt[16];
    __shared__ int wofs[16];
    __shared__ float ws[512];
    ws[j] = p ? w : 0.f;
    if (lane == 0) wcnt[warp] = __popc(mask);
    __syncthreads();
    if (j == 0) {
        int s = 0;
        for (int t = 0; t < 16; t++) { wofs[t] = s; s += wcnt[t]; }
        g_cnt[i] = s;
    }
    for (int stride = 256; stride > 0; stride >>= 1) {
        __syncthreads();
        if (j < stride) ws[j] += ws[j + stride];
    }
    if (j == 0) g_csum[i] = ws[0];
    __syncthreads();
    if (p) {
        int pos = wofs[warp] + __popc(mask & ((1u << lane) - 1u));
        g_colj[i*Nn + pos] = j;
        g_colw[i*Nn + pos] = w;
    }
}

// ---------------- per step kernel 1: s = A^T h (round-13 version) ----------
// grid 512 = (bp:32) x (mc:2) x (cq:8); warp owns 8 columns as 4 interleaved
// pairs; fp32 float2 output to g_s (coalesced).
struct AggAcc { float2 p[4]; };

__device__ __forceinline__ void agg_batch(const float* __restrict__ hsrc,
                                          const int* __restrict__ cj,
                                          const float* __restrict__ cw,
                                          int e, int b, int roff, AggAcc& A) {
    int4   ja = *(const int4*)(cj + e);
    int4   jb = *(const int4*)(cj + e + 4);
    float4 wa = *(const float4*)(cw + e);
    float4 wb = *(const float4*)(cw + e + 4);
    float2 h0 = *(const float2*)(hsrc + (((ja.x << 6) + b) << 6) + roff);
    float2 h1 = *(const float2*)(hsrc + (((ja.y << 6) + b) << 6) + roff);
    float2 h2 = *(const float2*)(hsrc + (((ja.z << 6) + b) << 6) + roff);
    float2 h3 = *(const float2*)(hsrc + (((ja.w << 6) + b) << 6) + roff);
    float2 h4 = *(const float2*)(hsrc + (((jb.x << 6) + b) << 6) + roff);
    float2 h5 = *(const float2*)(hsrc + (((jb.y << 6) + b) << 6) + roff);
    float2 h6 = *(const float2*)(hsrc + (((jb.z << 6) + b) << 6) + roff);
    float2 h7 = *(const float2*)(hsrc + (((jb.w << 6) + b) << 6) + roff);
    A.p[0].x += wa.x*h0.x; A.p[0].y += wa.x*h0.y;
    A.p[1].x += wa.y*h1.x; A.p[1].y += wa.y*h1.y;
    A.p[2].x += wa.z*h2.x; A.p[2].y += wa.z*h2.y;
    A.p[3].x += wa.w*h3.x; A.p[3].y += wa.w*h3.y;
    A.p[0].x += wb.x*h4.x; A.p[0].y += wb.x*h4.y;
    A.p[1].x += wb.y*h5.x; A.p[1].y += wb.y*h5.y;
    A.p[2].x += wb.z*h6.x; A.p[2].y += wb.z*h6.y;
    A.p[3].x += wb.w*h7.x; A.p[3].y += wb.w*h7.y;
}

__global__ __launch_bounds__(256)
void agg_kernel(const float* __restrict__ h0, int t) {
    const float* __restrict__ hsrc = (t == 0) ? h0 : g_h[t & 1];
    int bid = blockIdx.x;
    int bp = bid & 31, mc = (bid >> 5) & 1, cq = bid >> 6;   // cq 0..7
    int tid = threadIdx.x;
    int lane = tid & 31, wid = tid >> 5;
    int b = (bp << 1) + (lane >> 4);
    int roff = (mc << 5) + ((lane & 15) << 1);
    int colBase = (cq << 6) + (wid << 3);    // 8 columns per warp

    #pragma unroll 1
    for (int c = 0; c < 4; c++) {
        int i0 = colBase + 2*c;
        int i1 = i0 + 1;
        int cnt0 = g_cnt[i0], cnt1 = g_cnt[i1];
        const int*   cj0 = g_colj + i0*Nn;
        const float* cw0 = g_colw + i0*Nn;
        const int*   cj1 = g_colj + i1*Nn;
        const float* cw1 = g_colw + i1*Nn;
        AggAcc A0, A1;
        #pragma unroll
        for (int q = 0; q < 4; q++) { A0.p[q] = make_float2(0.f,0.f); A1.p[q] = make_float2(0.f,0.f); }

        #pragma unroll 2
        for (int u = 0; u < 4; u++) {
            agg_batch(hsrc, cj0, cw0, u*8, b, roff, A0);
            agg_batch(hsrc, cj1, cw1, u*8, b, roff, A1);
        }
        if (cnt0 > 32) {
            #pragma unroll 2
            for (int u = 4; u < 8; u++) agg_batch(hsrc, cj0, cw0, u*8, b, roff, A0);
            for (int e = 64; e < cnt0; e++) {
                float2 hv = *(const float2*)(hsrc + (((cj0[e] << 6) + b) << 6) + roff);
                A0.p[0].x += cw0[e]*hv.x; A0.p[0].y += cw0[e]*hv.y;
            }
        }
        if (cnt1 > 32) {
            #pragma unroll 2
            for (int u = 4; u < 8; u++) agg_batch(hsrc, cj1, cw1, u*8, b, roff, A1);
            for (int e = 64; e < cnt1; e++) {
                float2 hv = *(const float2*)(hsrc + (((cj1[e] << 6) + b) << 6) + roff);
                A1.p[0].x += cw1[e]*hv.x; A1.p[0].y += cw1[e]*hv.y;
            }
        }
        float2 r0, r1;
        r0.x = (A0.p[0].x + A0.p[1].x) + (A0.p[2].x + A0.p[3].x);
        r0.y = (A0.p[0].y + A0.p[1].y) + (A0.p[2].y + A0.p[3].y);
        r1.x = (A1.p[0].x + A1.p[1].x) + (A1.p[2].x + A1.p[3].x);
        r1.y = (A1.p[0].y + A1.p[1].y) + (A1.p[2].y + A1.p[3].y);
        *(float2*)(g_s + (((i0 << 6) + b) << 6) + roff) = r0;
        *(float2*)(g_s + (((i1 << 6) + b) << 6) + roff) = r1;
    }
}

// ---------------- per step kernel 2: HMMA GEMM + in-register GRU epilogue ----
// grid 512 (node n = 64 rows); 256 threads = 8 warps = (mw:2) x (nw:4).
// h-part A fragments direct from g_Ap (written by prior epilogue/init_frag);
// s-part staged from g_s into smem fragments (8-iter loop, 1 sync).
// Mainloop fully unrolled: static global-vs-shared A source per batch.
__global__ __launch_bounds__(256, 2)
void gru_mma_kernel(const float* __restrict__ inputs,
                    const float* __restrict__ b_ih,
                    const float* __restrict__ b_hh,
                    const float* __restrict__ h0,
                    int t) {
    __shared__ float tb[960];
    __shared__ uint32_t sfrag[4096];   // [s2][mt4][ktl4][lane32][rg4] = 16KB

    const float* __restrict__ hsrc = (t == 0) ? h0 : g_h[t & 1];
    float* __restrict__ hdst = g_h[(t + 1) & 1];
    const uint32_t* __restrict__ Apb = g_Ap[t & 1] + blockIdx.x*APN;
    uint32_t* __restrict__ Apn = g_Ap[(t + 1) & 1];

    int n = blockIdx.x;
    int rowBase = n << 6;
    int tid = threadIdx.x;

    for (int idx = tid; idx < 960; idx += 256) {
        float v = (idx < 192) ? b_ih[idx]
                : (idx < 384) ? b_hh[idx - 192]
                : (idx < 576) ? g_cvec[idx - 384]
                : g_Wx[idx - 576];
        tb[idx] = v;
    }
    // stage s-part fragments from g_s: (r 0..63) x (kps 0..31)
    #pragma unroll
    for (int it = 0; it < 8; it++) {
        int item = tid + it*256;
        int r = item >> 5, kps = item & 31;
        float2 v = *(const float2*)(g_s + (rowBase + r)*64 + kps*2);
        __nv_bfloat16 lo1, lo2, hi1, hi2;
        split2(v.x, lo1, lo2);
        split2(v.y, hi1, hi2);
        int mt = r >> 4, ktl = kps >> 3, q = kps & 7;
        int lf = ((r & 7) << 2) + (q & 3);
        int rg = ((q >> 2) << 1) + ((r & 15) >> 3);
        sfrag[((0*4 + mt)*4 + ktl)*128 + lf*4 + rg] = packbf(lo1, hi1);
        sfrag[((1*4 + mt)*4 + ktl)*128 + lf*4 + rg] = packbf(lo2, hi2);
    }
    __syncthreads();

    int lane = tid & 31;
    int w = tid >> 5;
    int mw = w & 1, nw = w >> 1;

    float c[2][8][4];
    #pragma unroll
    for (int i = 0; i < 2; i++)
        #pragma unroll
        for (int j = 0; j < 8; j++)
            #pragma unroll
            for (int q = 0; q < 4; q++) c[i][j][q] = 0.f;

    const uint32_t* __restrict__ Bp = g_Bp;
    uint32_t bbuf[2][8][2];
    {
        const uint32_t* bp = Bp + lane*2;
        #pragma unroll
        for (int j = 0; j < 8; j++)
            *(uint2*)bbuf[0][j] = *(const uint2*)(bp + (4*j + nw)*64);
    }
    #pragma unroll
    for (int bi = 0; bi < 24; bi++) {
        int par = bi & 1;
        if (bi < 23) {
            int bn = bi + 1;
            int cn = bn >> 3, ktn = bn & 7;
            int sbn = (cn == 2) ? 1 : 0;
            const uint32_t* bp = Bp + ((sbn*8 + ktn)*32)*64 + lane*2;
            #pragma unroll
            for (int j = 0; j < 8; j++)
                *(uint2*)bbuf[par ^ 1][j] = *(const uint2*)(bp + (4*j + nw)*64);
        }
        int combo = bi >> 3, kt = bi & 7;
        int sa = (combo == 1) ? 1 : 0;
        uint32_t a[2][4];
        #pragma unroll
        for (int mt2 = 0; mt2 < 2; mt2++) {
            if (kt < 4)
                *(uint4*)a[mt2] = *(const uint4*)(Apb +
                    ((sa*4 + mw*2 + mt2)*4 + kt)*128 + lane*4);
            else
                *(uint4*)a[mt2] = *(const uint4*)(sfrag +
                    ((sa*4 + mw*2 + mt2)*4 + (kt - 4))*128 + lane*4);
        }
        #pragma unroll
        for (int j = 0; j < 8; j++) {
            MMA16816(c[0][j], a[0], bbuf[par][j]);
            MMA16816(c[1][j], a[1], bbuf[par][j]);
        }
    }

    float cs = g_csum[n];
    int g4 = lane >> 2, tg = lane & 3;
    #pragma unroll
    for (int mt2 = 0; mt2 < 2; mt2++) {
        #pragma unroll
        for (int qh = 0; qh < 2; qh++) {
            int row = mw*32 + mt2*16 + g4 + 8*qh;
            int rowg = rowBase + row;
            const float* xp = inputs + ((row*Tt + t)*Nn + n)*Dd;
            float x0 = xp[0], x1 = xp[1];
            #pragma unroll
            for (int jg = 0; jg < 2; jg++) {
                int g0 = jg*32 + nw*8 + tg*2;
                float2 hold = *(const float2*)(hsrc + rowg*64 + g0);
                float hn[2];
                #pragma unroll
                for (int u = 0; u < 2; u++) {
                    int g = g0 + u;
                    int q = qh*2 + u;
                    float vr  = c[mt2][0*2 + jg][q] + tb[g]       + tb[192 + g]
                              + cs*tb[384 + g] + x0*tb[576 + g] + x1*tb[768 + g];
                    float vz  = c[mt2][1*2 + jg][q] + tb[64 + g]  + tb[256 + g]
                              + cs*tb[448 + g] + x0*tb[640 + g] + x1*tb[832 + g];
                    float vnh = c[mt2][2*2 + jg][q] + tb[320 + g];
                    float vns = c[mt2][3*2 + jg][q] + tb[128 + g]
                              + cs*tb[512 + g] + x0*tb[704 + g] + x1*tb[896 + g];
                    float rg = 1.f / (1.f + expf(-vr));
                    float zg = 1.f / (1.f + expf(-vz));
                    float nn = tanhf(vns + rg*vnh);
                    hn[u] = (1.f - zg)*nn + zg*((u == 0) ? hold.x : hold.y);
                }
                float2 hv = make_float2(hn[0], hn[1]);
                *(float2*)(hdst + rowg*64 + g0) = hv;
                store_frag(Apn + n*APN, row, g0 >> 1, hv);   // h-frag for t+1
            }
        }
    }
}

// ---------------- final readout ----------------
__global__ void out_kernel(const float* __restrict__ W_out,
                           const float* __restrict__ b_out,
                           float* __restrict__ out) {
    __shared__ float wo[12*64];
    __shared__ float bo[12];
    int tid = threadIdx.x;
    for (int idx = tid; idx < 768; idx += 256) wo[idx] = W_out[idx];
    if (tid < 12) bo[tid] = b_out[tid];
    __syncthreads();
    int row = blockIdx.x * 256 + tid;
    float accs[12];
    #pragma unroll
    for (int hh = 0; hh < 12; hh++) accs[hh] = bo[hh];
    for (int k = 0; k < 64; k++) {
        float hv = g_h[0][row*64 + k];
        #pragma unroll
        for (int hh = 0; hh < 12; hh++) accs[hh] += hv * wo[hh*64 + k];
    }
    int n = row >> 6, b = row & 63;
    #pragma unroll
    for (int hh = 0; hh < 12; hh++)
        out[(b*12 + hh)*512 + n] = accs[hh];
}

extern "C" void kernel_launch(void* const* d_in, const int* in_sizes, int n_in,
                              void* d_out, int out_size) {
    const float* inputs = (const float*)d_in[0];
    const float* h0     = (const float*)d_in[1];
    const float* adj    = (const float*)d_in[2];
    const float* W_msg  = (const float*)d_in[3];
    const float* b_msg  = (const float*)d_in[4];
    const float* W_ih   = (const float*)d_in[5];
    const float* W_hh   = (const float*)d_in[6];
    const float* b_ih   = (const float*)d_in[7];
    const float* b_hh   = (const float*)d_in[8];
    const float* W_out  = (const float*)d_in[9];
    const float* b_out  = (const float*)d_in[10];
    float* out = (float*)d_out;

    prep_kernel<<<67, 256>>>(W_hh, W_ih, W_msg, b_msg);
    build_csc<<<512, 512>>>(adj);
    init_frag<<<1024, 256>>>(h0);

    // t=11 writes g_h[0]; out_kernel reads g_h[0].
    for (int t = 0; t < Tt; t++) {
        agg_kernel<<<512, 256>>>(h0, t);
        gru_mma_kernel<<<512, 256>>>(inputs, b_ih, b_hh, h0, t);
    }
    out_kernel<<<128, 256>>>(W_out, b_out, out);
}

// round 16
// speedup vs baseline: 2.0289x; 2.0289x over previous
#include <cuda_runtime.h>
#include <cuda_bf16.h>
#include <math.h>
#include <stdint.h>

#define Bb 64
#define Tt 12
#define Nn 512
#define Dd 2
#define NB (Nn*Bb)   // 32768 rows (row = node*64 + batch)
#define APN 4096     // uint32 per node per buffer (h-part only: [s2][mt4][kt4][lane32][rg4])

// ---------------- device scratch ----------------
__device__ float g_h[2][NB*64];          // ping-pong hidden state (fp32)
__device__ float g_s[NB*64];             // s = A^T h (fp32)
// h-part A fragments per step parity (kt 0..3 only)
__device__ uint32_t g_Ap[2][Nn*APN];
// B fragments: [split][ktile 8][ntile 32][lane 32][reg 2]
__device__ uint32_t g_Bp[2*8*32*64];
__device__ float g_cvec[192];            // b_msg @ W_ih_m^T
__device__ float g_Wx[384];              // x weights [d][o]
__device__ float g_csum[Nn];
__device__ int   g_colj[Nn*Nn];
__device__ float g_colw[Nn*Nn];
__device__ int   g_cnt[Nn];

__device__ __forceinline__ uint32_t packbf(__nv_bfloat16 lo, __nv_bfloat16 hi) {
    return ((uint32_t)__bfloat16_as_ushort(hi) << 16) | (uint32_t)__bfloat16_as_ushort(lo);
}
__device__ __forceinline__ void split2(float v, __nv_bfloat16& b1, __nv_bfloat16& b2) {
    b1 = __float2bfloat16_rn(v);
    b2 = __float2bfloat16_rn(v - __bfloat162float(b1));
}
// h-part fragment index for value-pair at (r local row, kp = k/2 < 32); s = split
__device__ __forceinline__ int frag_idx(int s, int r, int kp) {
    int mt = r >> 4, kt = kp >> 3, q = kp & 7;
    int lf = ((r & 7) << 2) + (q & 3);
    int rg = ((q >> 2) << 1) + ((r & 15) >> 3);
    return ((s*4 + mt)*4 + kt)*128 + lf*4 + rg;
}
__device__ __forceinline__ void store_frag(uint32_t* Apn, int r, int kp, float2 v) {
    __nv_bfloat16 lo1, lo2, hi1, hi2;
    split2(v.x, lo1, lo2);
    split2(v.y, hi1, hi2);
    Apn[frag_idx(0, r, kp)] = packbf(lo1, hi1);
    Apn[frag_idx(1, r, kp)] = packbf(lo2, hi2);
}

#define MMA16816(c, a, b) \
    asm volatile("mma.sync.aligned.m16n8k16.row.col.f32.bf16.bf16.f32 " \
        "{%0,%1,%2,%3}, {%4,%5,%6,%7}, {%8,%9}, {%0,%1,%2,%3};" \
        : "+f"((c)[0]), "+f"((c)[1]), "+f"((c)[2]), "+f"((c)[3]) \
        : "r"((a)[0]), "r"((a)[1]), "r"((a)[2]), "r"((a)[3]), \
          "r"((b)[0]), "r"((b)[1]))

// ---------------- prep: pack B fragments + tables ----------------
__global__ void prep_kernel(const float* __restrict__ W_hh,
                            const float* __restrict__ W_ih,
                            const float* __restrict__ W_msg,
                            const float* __restrict__ b_msg) {
    int idx = blockIdx.x * 256 + threadIdx.x;
    if (idx < 16384) {                      // (n 0..255) x (kpair 0..63)
        int n = idx >> 6, kp = idx & 63;
        int p = n >> 6, g = n & 63;
        float w[2];
        #pragma unroll
        for (int u = 0; u < 2; u++) {
            int k = 2*kp + u;
            float v = 0.f;
            if (k < 64) {
                if (p < 3) v = W_hh[(p*64 + g)*64 + k];
            } else {
                int ks = k - 64;
                if (p != 2) {
                    int o = (p == 3) ? (128 + g) : (p*64 + g);
                    float s = 0.f;
                    for (int m = 0; m < 64; m++) s += W_msg[m*64 + ks] * W_ih[o*66 + m];
                    v = s;
                }
            }
            w[u] = v;
        }
        __nv_bfloat16 lo1, lo2, hi1, hi2;
        split2(w[0], lo1, lo2);
        split2(w[1], hi1, hi2);
        int nt = n >> 3, kt = kp >> 3, q = kp & 7;
        int lane = ((n & 7) << 2) + (q & 3);
        int reg = q >> 2;
        g_Bp[((0*8 + kt)*32 + nt)*64 + lane*2 + reg] = packbf(lo1, hi1);
        g_Bp[((1*8 + kt)*32 + nt)*64 + lane*2 + reg] = packbf(lo2, hi2);
    } else if (idx < 16384 + 384) {          // Wx[d][o]
        int j = idx - 16384;
        int d = j / 192, o = j - d*192;
        g_Wx[j] = W_ih[o*66 + 64 + d];
    } else if (idx < 16384 + 384 + 192) {    // cvec
        int o = idx - 16384 - 384;
        float s = 0.f;
        for (int m = 0; m < 64; m++) s += b_msg[m] * W_ih[o*66 + m];
        g_cvec[o] = s;
    }
}

// ---------------- one-time: h0 -> h-fragments of buffer 0 ----------------
__global__ void init_frag(const float* __restrict__ h0) {
    int item = blockIdx.x * 256 + threadIdx.x;   // (n, r, kp<32): 512*64*32 = 1M
    #pragma unroll
    for (int it = 0; it < 4; it++, item += 262144) {
        int n = item >> 11;
        int rem = item & 2047;
        int r = rem >> 5, kp = rem & 31;
        float2 v = *(const float2*)(h0 + (((n << 6) + r) << 6) + (kp << 1));
        store_frag(g_Ap[0] + n*APN, r, kp, v);
    }
}

// ---------------- deterministic CSC build + column sums (zero-padded to 64) --
__global__ void build_csc(const float* __restrict__ adj) {
    int i = blockIdx.x;
    int j = threadIdx.x;
    if (j < 64) { g_colj[i*Nn + j] = 0; g_colw[i*Nn + j] = 0.f; }
    float w = adj[j*Nn + i];
    bool p = (w > 0.f);
    unsigned mask = __ballot_sync(0xffffffffu, p);
    int warp = j >> 5, lane = j & 31;
    __shared__ int wcnt[16];
    __shared__ int wofs[16];
    __shared__ float ws[512];
    ws[j] = p ? w : 0.f;
    if (lane == 0) wcnt[warp] = __popc(mask);
    __syncthreads();
    if (j == 0) {
        int s = 0;
        for (int t = 0; t < 16; t++) { wofs[t] = s; s += wcnt[t]; }
        g_cnt[i] = s;
    }
    for (int stride = 256; stride > 0; stride >>= 1) {
        __syncthreads();
        if (j < stride) ws[j] += ws[j + stride];
    }
    if (j == 0) g_csum[i] = ws[0];
    __syncthreads();
    if (p) {
        int pos = wofs[warp] + __popc(mask & ((1u << lane) - 1u));
        g_colj[i*Nn + pos] = j;
        g_colw[i*Nn + pos] = w;
    }
}

// ---------------- per step kernel 1: s = A^T h (round-13 version) ----------
struct AggAcc { float2 p[4]; };

__device__ __forceinline__ void agg_batch(const float* __restrict__ hsrc,
                                          const int* __restrict__ cj,
                                          const float* __restrict__ cw,
                                          int e, int b, int roff, AggAcc& A) {
    int4   ja = *(const int4*)(cj + e);
    int4   jb = *(const int4*)(cj + e + 4);
    float4 wa = *(const float4*)(cw + e);
    float4 wb = *(const float4*)(cw + e + 4);
    float2 h0 = *(const float2*)(hsrc + (((ja.x << 6) + b) << 6) + roff);
    float2 h1 = *(const float2*)(hsrc + (((ja.y << 6) + b) << 6) + roff);
    float2 h2 = *(const float2*)(hsrc + (((ja.z << 6) + b) << 6) + roff);
    float2 h3 = *(const float2*)(hsrc + (((ja.w << 6) + b) << 6) + roff);
    float2 h4 = *(const float2*)(hsrc + (((jb.x << 6) + b) << 6) + roff);
    float2 h5 = *(const float2*)(hsrc + (((jb.y << 6) + b) << 6) + roff);
    float2 h6 = *(const float2*)(hsrc + (((jb.z << 6) + b) << 6) + roff);
    float2 h7 = *(const float2*)(hsrc + (((jb.w << 6) + b) << 6) + roff);
    A.p[0].x += wa.x*h0.x; A.p[0].y += wa.x*h0.y;
    A.p[1].x += wa.y*h1.x; A.p[1].y += wa.y*h1.y;
    A.p[2].x += wa.z*h2.x; A.p[2].y += wa.z*h2.y;
    A.p[3].x += wa.w*h3.x; A.p[3].y += wa.w*h3.y;
    A.p[0].x += wb.x*h4.x; A.p[0].y += wb.x*h4.y;
    A.p[1].x += wb.y*h5.x; A.p[1].y += wb.y*h5.y;
    A.p[2].x += wb.z*h6.x; A.p[2].y += wb.z*h6.y;
    A.p[3].x += wb.w*h7.x; A.p[3].y += wb.w*h7.y;
}

__global__ __launch_bounds__(256)
void agg_kernel(const float* __restrict__ h0, int t) {
    const float* __restrict__ hsrc = (t == 0) ? h0 : g_h[t & 1];
    int bid = blockIdx.x;
    int bp = bid & 31, mc = (bid >> 5) & 1, cq = bid >> 6;   // cq 0..7
    int tid = threadIdx.x;
    int lane = tid & 31, wid = tid >> 5;
    int b = (bp << 1) + (lane >> 4);
    int roff = (mc << 5) + ((lane & 15) << 1);
    int colBase = (cq << 6) + (wid << 3);    // 8 columns per warp

    #pragma unroll 1
    for (int c = 0; c < 4; c++) {
        int i0 = colBase + 2*c;
        int i1 = i0 + 1;
        int cnt0 = g_cnt[i0], cnt1 = g_cnt[i1];
        const int*   cj0 = g_colj + i0*Nn;
        const float* cw0 = g_colw + i0*Nn;
        const int*   cj1 = g_colj + i1*Nn;
        const float* cw1 = g_colw + i1*Nn;
        AggAcc A0, A1;
        #pragma unroll
        for (int q = 0; q < 4; q++) { A0.p[q] = make_float2(0.f,0.f); A1.p[q] = make_float2(0.f,0.f); }

        #pragma unroll 2
        for (int u = 0; u < 4; u++) {
            agg_batch(hsrc, cj0, cw0, u*8, b, roff, A0);
            agg_batch(hsrc, cj1, cw1, u*8, b, roff, A1);
        }
        if (cnt0 > 32) {
            #pragma unroll 2
            for (int u = 4; u < 8; u++) agg_batch(hsrc, cj0, cw0, u*8, b, roff, A0);
            for (int e = 64; e < cnt0; e++) {
                float2 hv = *(const float2*)(hsrc + (((cj0[e] << 6) + b) << 6) + roff);
                A0.p[0].x += cw0[e]*hv.x; A0.p[0].y += cw0[e]*hv.y;
            }
        }
        if (cnt1 > 32) {
            #pragma unroll 2
            for (int u = 4; u < 8; u++) agg_batch(hsrc, cj1, cw1, u*8, b, roff, A1);
            for (int e = 64; e < cnt1; e++) {
                float2 hv = *(const float2*)(hsrc + (((cj1[e] << 6) + b) << 6) + roff);
                A1.p[0].x += cw1[e]*hv.x; A1.p[0].y += cw1[e]*hv.y;
            }
        }
        float2 r0, r1;
        r0.x = (A0.p[0].x + A0.p[1].x) + (A0.p[2].x + A0.p[3].x);
        r0.y = (A0.p[0].y + A0.p[1].y) + (A0.p[2].y + A0.p[3].y);
        r1.x = (A1.p[0].x + A1.p[1].x) + (A1.p[2].x + A1.p[3].x);
        r1.y = (A1.p[0].y + A1.p[1].y) + (A1.p[2].y + A1.p[3].y);
        *(float2*)(g_s + (((i0 << 6) + b) << 6) + roff) = r0;
        *(float2*)(g_s + (((i1 << 6) + b) << 6) + roff) = r1;
    }
}

// ---------------- per step kernel 2: HMMA GEMM + in-register GRU epilogue ----
// h-part A fragments direct from g_Ap; s-part staged from g_s into smem
// fragments (8-iter loop, 1 sync). Main loop: #pragma unroll 2 (NOT full —
// full unroll caused register spills in round 15).
__global__ __launch_bounds__(256, 2)
void gru_mma_kernel(const float* __restrict__ inputs,
                    const float* __restrict__ b_ih,
                    const float* __restrict__ b_hh,
                    const float* __restrict__ h0,
                    int t) {
    __shared__ float tb[960];
    __shared__ uint32_t sfrag[4096];   // [s2][mt4][ktl4][lane32][rg4] = 16KB

    const float* __restrict__ hsrc = (t == 0) ? h0 : g_h[t & 1];
    float* __restrict__ hdst = g_h[(t + 1) & 1];
    const uint32_t* __restrict__ Apb = g_Ap[t & 1] + blockIdx.x*APN;
    uint32_t* __restrict__ Apn = g_Ap[(t + 1) & 1];

    int n = blockIdx.x;
    int rowBase = n << 6;
    int tid = threadIdx.x;

    for (int idx = tid; idx < 960; idx += 256) {
        float v = (idx < 192) ? b_ih[idx]
                : (idx < 384) ? b_hh[idx - 192]
                : (idx < 576) ? g_cvec[idx - 384]
                : g_Wx[idx - 576];
        tb[idx] = v;
    }
    // stage s-part fragments from g_s: (r 0..63) x (kps 0..31)
    #pragma unroll
    for (int it = 0; it < 8; it++) {
        int item = tid + it*256;
        int r = item >> 5, kps = item & 31;
        float2 v = *(const float2*)(g_s + (rowBase + r)*64 + kps*2);
        __nv_bfloat16 lo1, lo2, hi1, hi2;
        split2(v.x, lo1, lo2);
        split2(v.y, hi1, hi2);
        int mt = r >> 4, ktl = kps >> 3, q = kps & 7;
        int lf = ((r & 7) << 2) + (q & 3);
        int rg = ((q >> 2) << 1) + ((r & 15) >> 3);
        sfrag[((0*4 + mt)*4 + ktl)*128 + lf*4 + rg] = packbf(lo1, hi1);
        sfrag[((1*4 + mt)*4 + ktl)*128 + lf*4 + rg] = packbf(lo2, hi2);
    }
    __syncthreads();

    int lane = tid & 31;
    int w = tid >> 5;
    int mw = w & 1, nw = w >> 1;

    float c[2][8][4];
    #pragma unroll
    for (int i = 0; i < 2; i++)
        #pragma unroll
        for (int j = 0; j < 8; j++)
            #pragma unroll
            for (int q = 0; q < 4; q++) c[i][j][q] = 0.f;

    const uint32_t* __restrict__ Bp = g_Bp;
    uint32_t bbuf[2][8][2];
    {
        const uint32_t* bp = Bp + lane*2;
        #pragma unroll
        for (int j = 0; j < 8; j++)
            *(uint2*)bbuf[0][j] = *(const uint2*)(bp + (4*j + nw)*64);
    }
    #pragma unroll 2
    for (int bi = 0; bi < 24; bi++) {
        int par = bi & 1;
        if (bi < 23) {
            int bn = bi + 1;
            int cn = bn >> 3, ktn = bn & 7;
            int sbn = (cn == 2) ? 1 : 0;
            const uint32_t* bp = Bp + ((sbn*8 + ktn)*32)*64 + lane*2;
            #pragma unroll
            for (int j = 0; j < 8; j++)
                *(uint2*)bbuf[par ^ 1][j] = *(const uint2*)(bp + (4*j + nw)*64);
        }
        int combo = bi >> 3, kt = bi & 7;
        int sa = (combo == 1) ? 1 : 0;
        uint32_t a[2][4];
        #pragma unroll
        for (int mt2 = 0; mt2 < 2; mt2++) {
            if (kt < 4)
                *(uint4*)a[mt2] = *(const uint4*)(Apb +
                    ((sa*4 + mw*2 + mt2)*4 + kt)*128 + lane*4);
            else
                *(uint4*)a[mt2] = *(const uint4*)(sfrag +
                    ((sa*4 + mw*2 + mt2)*4 + (kt - 4))*128 + lane*4);
        }
        #pragma unroll
        for (int j = 0; j < 8; j++) {
            MMA16816(c[0][j], a[0], bbuf[par][j]);
            MMA16816(c[1][j], a[1], bbuf[par][j]);
        }
    }

    float cs = g_csum[n];
    int g4 = lane >> 2, tg = lane & 3;
    #pragma unroll
    for (int mt2 = 0; mt2 < 2; mt2++) {
        #pragma unroll
        for (int qh = 0; qh < 2; qh++) {
            int row = mw*32 + mt2*16 + g4 + 8*qh;
            int rowg = rowBase + row;
            const float* xp = inputs + ((row*Tt + t)*Nn + n)*Dd;
            float x0 = xp[0], x1 = xp[1];
            #pragma unroll
            for (int jg = 0; jg < 2; jg++) {
                int g0 = jg*32 + nw*8 + tg*2;
                float2 hold = *(const float2*)(hsrc + rowg*64 + g0);
                float hn[2];
                #pragma unroll
                for (int u = 0; u < 2; u++) {
                    int g = g0 + u;
                    int q = qh*2 + u;
                    float vr  = c[mt2][0*2 + jg][q] + tb[g]       + tb[192 + g]
                              + cs*tb[384 + g] + x0*tb[576 + g] + x1*tb[768 + g];
                    float vz  = c[mt2][1*2 + jg][q] + tb[64 + g]  + tb[256 + g]
                              + cs*tb[448 + g] + x0*tb[640 + g] + x1*tb[832 + g];
                    float vnh = c[mt2][2*2 + jg][q] + tb[320 + g];
                    float vns = c[mt2][3*2 + jg][q] + tb[128 + g]
                              + cs*tb[512 + g] + x0*tb[704 + g] + x1*tb[896 + g];
                    float rg = 1.f / (1.f + expf(-vr));
                    float zg = 1.f / (1.f + expf(-vz));
                    float nn = tanhf(vns + rg*vnh);
                    hn[u] = (1.f - zg)*nn + zg*((u == 0) ? hold.x : hold.y);
                }
                float2 hv = make_float2(hn[0], hn[1]);
                *(float2*)(hdst + rowg*64 + g0) = hv;
                store_frag(Apn + n*APN, row, g0 >> 1, hv);   // h-frag for t+1
            }
        }
    }
}

// ---------------- final readout ----------------
__global__ void out_kernel(const float* __restrict__ W_out,
                           const float* __restrict__ b_out,
                           float* __restrict__ out) {
    __shared__ float wo[12*64];
    __shared__ float bo[12];
    int tid = threadIdx.x;
    for (int idx = tid; idx < 768; idx += 256) wo[idx] = W_out[idx];
    if (tid < 12) bo[tid] = b_out[tid];
    __syncthreads();
    int row = blockIdx.x * 256 + tid;
    float accs[12];
    #pragma unroll
    for (int hh = 0; hh < 12; hh++) accs[hh] = bo[hh];
    for (int k = 0; k < 64; k++) {
        float hv = g_h[0][row*64 + k];
        #pragma unroll
        for (int hh = 0; hh < 12; hh++) accs[hh] += hv * wo[hh*64 + k];
    }
    int n = row >> 6, b = row & 63;
    #pragma unroll
    for (int hh = 0; hh < 12; hh++)
        out[(b*12 + hh)*512 + n] = accs[hh];
}

extern "C" void kernel_launch(void* const* d_in, const int* in_sizes, int n_in,
                              void* d_out, int out_size) {
    const float* inputs = (const float*)d_in[0];
    const float* h0     = (const float*)d_in[1];
    const float* adj    = (const float*)d_in[2];
    const float* W_msg  = (const float*)d_in[3];
    const float* b_msg  = (const float*)d_in[4];
    const float* W_ih   = (const float*)d_in[5];
    const float* W_hh   = (const float*)d_in[6];
    const float* b_ih   = (const float*)d_in[7];
    const float* b_hh   = (const float*)d_in[8];
    const float* W_out  = (const float*)d_in[9];
    const float* b_out  = (const float*)d_in[10];
    float* out = (float*)d_out;

    prep_kernel<<<67, 256>>>(W_hh, W_ih, W_msg, b_msg);
    build_csc<<<512, 512>>>(adj);
    init_frag<<<1024, 256>>>(h0);

    // t=11 writes g_h[0]; out_kernel reads g_h[0].
    for (int t = 0; t < Tt; t++) {
        agg_kernel<<<512, 256>>>(h0, t);
        gru_mma_kernel<<<512, 256>>>(inputs, b_ih, b_hh, h0, t);
    }
    out_kernel<<<128, 256>>>(W_out, b_out, out);
}